// round 6
// baseline (speedup 1.0000x reference)
#include <cuda_runtime.h>

#define H    4096
#define K    32
#define WO   4065
#define OCOLS 96          // outputs per warp strip
#define NW   4            // warps per CTA
#define NT   128
#define GX   11           // grid.x ; warp-strip id = wid*GX + bx  (44 strips, 43 live)
#define NCH  27
#define RCH  151          // 27*151 = 4077 >= 4065

__device__ __forceinline__ unsigned pk(float lo, float hi) {
    unsigned u;
    asm("cvt.rn.bf16x2.f32 %0, %1, %2;" : "=r"(u) : "f"(hi), "f"(lo));
    return u;
}
__device__ __forceinline__ float upLo(unsigned u) { return __uint_as_float(u << 16); }
__device__ __forceinline__ float upHi(unsigned u) { return __uint_as_float(u & 0xffff0000u); }

__global__ void __launch_bounds__(NT)
fused(const float* __restrict__ img,
      const float* __restrict__ som,
      const float* __restrict__ var,
      float* __restrict__ out)
{
    __shared__ float4   simg4[K * 8];          //  4 KB  img rows as float4
    __shared__ uint2    ring[NW][K][32];       // 32 KB  bf16x2 pairs (4 cols/lane)
    __shared__ float    P[NW][128];            //  2 KB  per-warp prefix row

    const int tid = threadIdx.x, wid = tid >> 5, lane = tid & 31;

    {
        float* simg = (float*)simg4;
        for (int i = tid; i < K * K; i += NT) simg[i] = img[i];
    }
    __syncthreads();                           // only CTA barrier

    const int sid = wid * GX + blockIdx.x;     // 0..43
    const int xs  = sid * OCOLS;
    if (xs >= WO) return;                      // one dead warp config

    const int gx0   = xs + 4 * lane;           // this lane's 4 load cols
    const bool valid = gx0 < H;                // whole-float4 validity (gx0 % 4 == 0)
    const int j0   = blockIdx.y * RCH;
    const int jend = min(j0 + RCH, WO);
    const int yend = jend + K - 2;             // inclusive last input row (<= 4095)

    const int imgIdx = lane & 7;               // (gx0 & 31) / 4  since xs % 32 == 0

    float vs0 = 0.f, vs1 = 0.f, vs2 = 0.f, vs3 = 0.f;

    // depth-2 prefetch
    size_t off = (size_t)j0 * H + gx0;
    float4 sA = {0,0,0,0}, wA = {1,1,1,1}, sB = {0,0,0,0}, wB = {1,1,1,1};
    if (valid) {
        sA = *(const float4*)(som + off);
        wA = *(const float4*)(var + off);
        if (j0 + 1 <= yend) {
            sB = *(const float4*)(som + off + H);
            wB = *(const float4*)(var + off + H);
        }
    }
    off += 2 * (size_t)H;

    for (int y = j0; y <= yend; y++) {
        const float4 s4 = sA, w4 = wA;
        sA = sB; wA = wB;
        if (valid && y + 2 <= yend) {
            sB = *(const float4*)(som + off);
            wB = *(const float4*)(var + off);
        }
        off += H;

        // variance-weighted squared distance, 4 cols
        const float4 iv = simg4[((y & 31) << 3) + imgIdx];
        float d0 = 0.f, d1 = 0.f, d2 = 0.f, d3 = 0.f;
        if (valid) {
            float f0 = iv.x - s4.x, f1 = iv.y - s4.y;
            float f2 = iv.z - s4.z, f3 = iv.w - s4.w;
            d0 = __fdividef(f0 * f0, w4.x + 1e-8f);
            d1 = __fdividef(f1 * f1, w4.y + 1e-8f);
            d2 = __fdividef(f2 * f2, w4.z + 1e-8f);
            d3 = __fdividef(f3 * f3, w4.w + 1e-8f);
        }

        // vertical sliding sums with bf16 ring history
        uint2* rs = &ring[wid][y & 31][lane];
        float o0 = 0.f, o1 = 0.f, o2 = 0.f, o3 = 0.f;
        if (y >= j0 + K) {
            uint2 r = *rs;
            o0 = upLo(r.x); o1 = upHi(r.x);
            o2 = upLo(r.y); o3 = upHi(r.y);
        }
        uint2 nw2; nw2.x = pk(d0, d1); nw2.y = pk(d2, d3);
        *rs = nw2;
        vs0 += d0 - o0; vs1 += d1 - o1; vs2 += d2 - o2; vs3 += d3 - o3;

        if (y >= j0 + K - 1) {
            // 128-wide prefix over vs via one warp scan
            const float t0 = vs0, t1 = t0 + vs1, t2 = t1 + vs2, t3 = t2 + vs3;
            float s = t3;
#pragma unroll
            for (int dd = 1; dd < 32; dd <<= 1) {
                float u = __shfl_up_sync(0xffffffffu, s, dd);
                if (lane >= dd) s += u;
            }
            const float excl = s - t3;
            __syncwarp();                       // WAR on P vs previous row's reads
            float4 pv = make_float4(excl + t0, excl + t1, excl + t2, excl + t3);
            ((float4*)P[wid])[lane] = pv;
            __syncwarp();

            const int j = y - (K - 1);          // output row (always < jend here)
            float* orow = out + (size_t)j * WO;
#pragma unroll
            for (int q = 0; q < 3; q++) {
                int x = lane + q * 32;          // local output col, 0..95
                float r = P[wid][x + 31] - (x ? P[wid][x - 1] : 0.f);
                int gxo = xs + x;
                if (gxo < WO) orow[gxo] = r;
            }
        }
    }
}

extern "C" void kernel_launch(void* const* d_in, const int* in_sizes, int n_in,
                              void* d_out, int out_size)
{
    const float* img = (const float*)d_in[0];   // [32,32]
    const float* som = (const float*)d_in[1];   // [4096,4096]
    const float* var = (const float*)d_in[2];   // [4096,4096]
    float*       out = (float*)d_out;           // [4065,4065]

    dim3 grid(GX, NCH);                         // 297 CTAs, 4 warp-strips each
    fused<<<grid, NT>>>(img, som, var, out);
}

// round 7
// speedup vs baseline: 2.0742x; 2.0742x over previous
#include <cuda_runtime.h>
#include <cuda_fp16.h>

#define H     4096
#define K     32
#define WO    4065
#define HP2   2048            // half2 (uint) pitch of scratch rows
#define RCH2  96              // output rows per pass-2 chunk

// fp16 scratch: 4096 rows x 2048 half2 = 33.5 MB
__device__ unsigned g_tmp[(size_t)H * HP2];

__device__ __forceinline__ int sk(int x) { return x + (x >> 4); }   // lane stride 17
__device__ __forceinline__ int hs(int i) { return i + (i >> 3); }   // stride-9 skew

// ---------------------------------------------------------------------------
// Pass 1: per row y: dist = (img - som)^2 / (var + eps), horizontal 32-wide
// box sum, store as fp16. One 256-thread CTA per row, float4 loads.
// ---------------------------------------------------------------------------
__global__ void __launch_bounds__(256, 8)
row_pass(const float* __restrict__ img,
         const float* __restrict__ som,
         const float* __restrict__ var)
{
    __shared__ float d[4352];          // skewed dist row (sk(4095)=4350)
    __shared__ float irow[32];

    const int y = blockIdx.x;
    const int t = threadIdx.x;

    if (t < 32) irow[t] = img[((y & 31) << 5) + t];
    __syncthreads();

    const float4* s4 = (const float4*)(som + (size_t)y * H);
    const float4* v4 = (const float4*)(var + (size_t)y * H);
    const float4  iv = ((const float4*)irow)[t & 7];   // (4*(t+256k))&31 = 4*(t&7)

#pragma unroll
    for (int k = 0; k < 4; k++) {
        int i4 = t + (k << 8);                 // float4 index 0..1023
        float4 s = s4[i4];
        float4 v = v4[i4];
        int x = i4 << 2;
        float f0 = iv.x - s.x, f1 = iv.y - s.y, f2 = iv.z - s.z, f3 = iv.w - s.w;
        d[sk(x)]     = __fdividef(f0 * f0, v.x + 1e-8f);
        d[sk(x + 1)] = __fdividef(f1 * f1, v.y + 1e-8f);
        d[sk(x + 2)] = __fdividef(f2 * f2, v.z + 1e-8f);
        d[sk(x + 3)] = __fdividef(f3 * f3, v.w + 1e-8f);
    }
    __syncthreads();

    // 16-output sliding window per thread
    const int base = t << 4;
    const int jmax = (base < WO) ? min(16, WO - base) : 0;
    float res[16];
#pragma unroll
    for (int j = 0; j < 16; j++) res[j] = 0.f;

    if (jmax > 0) {
        float s = 0.f;
#pragma unroll
        for (int i = 0; i < K; i++) s += d[sk(base + i)];
        res[0] = s;
#pragma unroll
        for (int j = 1; j < 16; j++) {
            s += d[sk(base + j + K - 1)] - d[sk(base + j - 1)];
            if (j < jmax) res[j] = s;
        }
    }
    __syncthreads();   // all window reads of d done

    // restage as half2 into d (reinterpreted), skewed stride-9
    unsigned* hbuf = (unsigned*)d;
#pragma unroll
    for (int p = 0; p < 8; p++) {
        __half2 h = __floats2half2_rn(res[2 * p], res[2 * p + 1]);
        hbuf[hs((t << 3) + p)] = *(unsigned*)&h;
    }
    __syncthreads();

    // coalesced scratch store: 2033 half2 per row
    unsigned* grow = g_tmp + (size_t)y * HP2;
#pragma unroll
    for (int k = 0; k < 8; k++) {
        int idx = t + (k << 8);
        if (idx < 2033) grow[idx] = hbuf[hs(idx)];
    }
}

// ---------------------------------------------------------------------------
// Pass 2: vertical 32-wide running box sum. Thread owns one half2 column
// (2 output cols), fp32 accumulators, coalesced loads/stores.
// ---------------------------------------------------------------------------
__global__ void __launch_bounds__(256)
col_pass(float* __restrict__ out)
{
    const int c2 = blockIdx.x * 256 + threadIdx.x;   // half2 column
    if (c2 >= 2033) return;
    const int x0 = c2 << 1;                          // output col (<= 4064)
    const bool x1ok = (x0 + 1) < WO;

    const int j0   = blockIdx.y * RCH2;
    const int jend = min(j0 + RCH2, WO);
    const unsigned* col = g_tmp + c2;

    float s0 = 0.f, s1 = 0.f;
#pragma unroll 8
    for (int r = 0; r < K; r++) {
        unsigned u = col[(size_t)(j0 + r) * HP2];
        float2 v = __half22float2(*(const __half2*)&u);
        s0 += v.x; s1 += v.y;
    }
    float* o = out + (size_t)j0 * WO + x0;
    o[0] = s0;
    if (x1ok) o[1] = s1;

#pragma unroll 4
    for (int j = j0 + 1; j < jend; j++) {
        unsigned ua = col[(size_t)(j + K - 1) * HP2];
        unsigned ub = col[(size_t)(j - 1) * HP2];
        float2 a = __half22float2(*(const __half2*)&ua);
        float2 b = __half22float2(*(const __half2*)&ub);
        s0 += a.x - b.x;
        s1 += a.y - b.y;
        o += WO;
        o[0] = s0;
        if (x1ok) o[1] = s1;
    }
}

// ---------------------------------------------------------------------------
extern "C" void kernel_launch(void* const* d_in, const int* in_sizes, int n_in,
                              void* d_out, int out_size)
{
    const float* img = (const float*)d_in[0];   // [32,32]
    const float* som = (const float*)d_in[1];   // [4096,4096]
    const float* var = (const float*)d_in[2];   // [4096,4096]
    float*       out = (float*)d_out;           // [4065,4065]

    row_pass<<<H, 256>>>(img, som, var);

    dim3 grid2((2033 + 255) / 256,              // 8
               (WO + RCH2 - 1) / RCH2);         // 43  -> 344 CTAs
    col_pass<<<grid2, 256>>>(out);
}

// round 8
// speedup vs baseline: 2.3861x; 1.1504x over previous
#include <cuda_runtime.h>
#include <cuda_fp16.h>

#define H     4096
#define K     32
#define WO    4065
#define HP2   2048            // half2 (uint) pitch of scratch rows
#define RCH2  96              // output rows per pass-2 chunk

// fp16 scratch: 4096 rows x 2048 half2 = 33.5 MB
__device__ unsigned g_tmp[(size_t)H * HP2];

__device__ __forceinline__ int sk(int x) { return x + (x >> 4); }   // lane stride 17
__device__ __forceinline__ int hs(int i) { return i + (i >> 3); }   // stride-9 skew

__device__ __forceinline__ float4 ldcs4(const float4* p) {
    float4 r;
    asm volatile("ld.global.cs.v4.f32 {%0,%1,%2,%3}, [%4];"
                 : "=f"(r.x), "=f"(r.y), "=f"(r.z), "=f"(r.w) : "l"(p));
    return r;
}

// ---------------------------------------------------------------------------
// Pass 1: per row y: dist = (img - som)^2 / (var + eps), horizontal 32-wide
// box sum, store fp16. One 256-thread CTA per row. Streaming loads (.cs)
// keep L2 free so the scratch stays resident for pass 2.
// ---------------------------------------------------------------------------
__global__ void __launch_bounds__(256, 8)
row_pass(const float* __restrict__ img,
         const float* __restrict__ som,
         const float* __restrict__ var)
{
    __shared__ float d[4352];          // skewed dist row (sk(4095)=4350)
    __shared__ float irow[32];

    const int y = blockIdx.x;
    const int t = threadIdx.x;

    if (t < 32) irow[t] = img[((y & 31) << 5) + t];
    __syncthreads();

    const float4* s4 = (const float4*)(som + (size_t)y * H);
    const float4* v4 = (const float4*)(var + (size_t)y * H);
    const float4  iv = ((const float4*)irow)[t & 7];   // (4*(t+256k))&31 = 4*(t&7)

#pragma unroll
    for (int k = 0; k < 4; k++) {
        int i4 = t + (k << 8);                 // float4 index 0..1023
        float4 s = ldcs4(s4 + i4);
        float4 v = ldcs4(v4 + i4);
        int x = i4 << 2;
        float f0 = iv.x - s.x, f1 = iv.y - s.y, f2 = iv.z - s.z, f3 = iv.w - s.w;
        d[sk(x)]     = __fdividef(f0 * f0, v.x + 1e-8f);
        d[sk(x + 1)] = __fdividef(f1 * f1, v.y + 1e-8f);
        d[sk(x + 2)] = __fdividef(f2 * f2, v.z + 1e-8f);
        d[sk(x + 3)] = __fdividef(f3 * f3, v.w + 1e-8f);
    }
    __syncthreads();

    // 16-output sliding window per thread
    const int base = t << 4;
    const int jmax = (base < WO) ? min(16, WO - base) : 0;
    float res[16];
#pragma unroll
    for (int j = 0; j < 16; j++) res[j] = 0.f;

    if (jmax > 0) {
        float s = 0.f;
#pragma unroll
        for (int i = 0; i < K; i++) s += d[sk(base + i)];
        res[0] = s;
#pragma unroll
        for (int j = 1; j < 16; j++) {
            s += d[sk(base + j + K - 1)] - d[sk(base + j - 1)];
            if (j < jmax) res[j] = s;
        }
    }
    __syncthreads();   // all window reads of d done

    // restage as half2 (skewed), then coalesced scratch store
    unsigned* hbuf = (unsigned*)d;
#pragma unroll
    for (int p = 0; p < 8; p++) {
        __half2 h = __floats2half2_rn(res[2 * p], res[2 * p + 1]);
        hbuf[hs((t << 3) + p)] = *(unsigned*)&h;
    }
    __syncthreads();

    unsigned* grow = g_tmp + (size_t)y * HP2;
#pragma unroll
    for (int k = 0; k < 8; k++) {
        int idx = t + (k << 8);
        if (idx < 2033) grow[idx] = hbuf[hs(idx)];
    }
}

// ---------------------------------------------------------------------------
// Pass 2: vertical 32-wide running box sum, batch-8 rows with all 16 loads
// issued up front (MLP=16/thread). Thread owns one half2 column (2 out cols).
// ---------------------------------------------------------------------------
__global__ void __launch_bounds__(256)
col_pass(float* __restrict__ out)
{
    const int c2 = blockIdx.x * 256 + threadIdx.x;   // half2 column
    if (c2 >= 2033) return;
    const int x0 = c2 << 1;
    const bool x1ok = (x0 + 1) < WO;

    const int j0   = blockIdx.y * RCH2;
    const int n    = min(RCH2, WO - j0);             // outputs this chunk
    const unsigned* col = g_tmp + c2;

    // warmup: 32 independent loads
    float s0 = 0.f, s1 = 0.f;
    {
        unsigned u[K];
#pragma unroll
        for (int r = 0; r < K; r++)
            u[r] = col[(size_t)(j0 + r) * HP2];
#pragma unroll
        for (int r = 0; r < K; r++) {
            float2 v = __half22float2(*(const __half2*)&u[r]);
            s0 += v.x; s1 += v.y;
        }
    }
    {
        float* o = out + (size_t)j0 * WO + x0;
        o[0] = s0;
        if (x1ok) o[1] = s1;
    }

    // main loop: blocks of 8 rows, 16 loads in flight per block
    for (int r = 1; r < n; r += 8) {
        const int m = min(8, n - r);
        unsigned ua[8], ub[8];
#pragma unroll
        for (int i = 0; i < 8; i++) {
            if (i < m) {
                ua[i] = col[(size_t)(j0 + r + i + K - 1) * HP2];
                ub[i] = col[(size_t)(j0 + r + i - 1) * HP2];
            }
        }
#pragma unroll
        for (int i = 0; i < 8; i++) {
            if (i < m) {
                float2 a = __half22float2(*(const __half2*)&ua[i]);
                float2 b = __half22float2(*(const __half2*)&ub[i]);
                s0 += a.x - b.x;
                s1 += a.y - b.y;
                float* o = out + (size_t)(j0 + r + i) * WO + x0;
                o[0] = s0;
                if (x1ok) o[1] = s1;
            }
        }
    }
}

// ---------------------------------------------------------------------------
extern "C" void kernel_launch(void* const* d_in, const int* in_sizes, int n_in,
                              void* d_out, int out_size)
{
    const float* img = (const float*)d_in[0];   // [32,32]
    const float* som = (const float*)d_in[1];   // [4096,4096]
    const float* var = (const float*)d_in[2];   // [4096,4096]
    float*       out = (float*)d_out;           // [4065,4065]

    row_pass<<<H, 256>>>(img, som, var);

    dim3 grid2((2033 + 255) / 256,              // 8
               (WO + RCH2 - 1) / RCH2);         // 43 -> 344 CTAs
    col_pass<<<grid2, 256>>>(out);
}

// round 9
// speedup vs baseline: 2.5724x; 1.0781x over previous
#include <cuda_runtime.h>
#include <cuda_fp16.h>

#define H     4096
#define K     32
#define WO    4065
#define HP2   2048            // half2 (uint) pitch of scratch rows
#define RCH2  48              // output rows per pass-2 chunk -> 85 chunks

// fp16 scratch: 4096 rows x 2048 half2 = 33.5 MB (L2-resident by design)
__device__ unsigned g_tmp[(size_t)H * HP2];

__device__ __forceinline__ int sk(int x) { return x + (x >> 4); }   // lane stride 17
__device__ __forceinline__ int hs(int i) { return i + (i >> 3); }   // stride-9 skew

__device__ __forceinline__ float4 ldcs4(const float4* p) {
    float4 r;
    asm volatile("ld.global.cs.v4.f32 {%0,%1,%2,%3}, [%4];"
                 : "=f"(r.x), "=f"(r.y), "=f"(r.z), "=f"(r.w) : "l"(p));
    return r;
}
__device__ __forceinline__ void stcs(float* p, float v) {
    asm volatile("st.global.cs.f32 [%0], %1;" :: "l"(p), "f"(v));
}

// ---------------------------------------------------------------------------
// Pass 1: dist = (img - som)^2/(var+eps), horizontal 32-wide box sum, fp16
// scratch. .cs loads keep L2 free so the scratch stays resident for pass 2.
// ---------------------------------------------------------------------------
__global__ void __launch_bounds__(256, 8)
row_pass(const float* __restrict__ img,
         const float* __restrict__ som,
         const float* __restrict__ var)
{
    __shared__ float d[4352];          // skewed dist row (sk(4095)=4350)
    __shared__ float irow[32];

    const int y = blockIdx.x;
    const int t = threadIdx.x;

    if (t < 32) irow[t] = img[((y & 31) << 5) + t];
    __syncthreads();

    const float4* s4 = (const float4*)(som + (size_t)y * H);
    const float4* v4 = (const float4*)(var + (size_t)y * H);
    const float4  iv = ((const float4*)irow)[t & 7];

#pragma unroll
    for (int k = 0; k < 4; k++) {
        int i4 = t + (k << 8);
        float4 s = ldcs4(s4 + i4);
        float4 v = ldcs4(v4 + i4);
        int x = i4 << 2;
        float f0 = iv.x - s.x, f1 = iv.y - s.y, f2 = iv.z - s.z, f3 = iv.w - s.w;
        d[sk(x)]     = __fdividef(f0 * f0, v.x + 1e-8f);
        d[sk(x + 1)] = __fdividef(f1 * f1, v.y + 1e-8f);
        d[sk(x + 2)] = __fdividef(f2 * f2, v.z + 1e-8f);
        d[sk(x + 3)] = __fdividef(f3 * f3, v.w + 1e-8f);
    }
    __syncthreads();

    const int base = t << 4;
    const int jmax = (base < WO) ? min(16, WO - base) : 0;
    float res[16];
#pragma unroll
    for (int j = 0; j < 16; j++) res[j] = 0.f;

    if (jmax > 0) {
        float s = 0.f;
#pragma unroll
        for (int i = 0; i < K; i++) s += d[sk(base + i)];
        res[0] = s;
#pragma unroll
        for (int j = 1; j < 16; j++) {
            s += d[sk(base + j + K - 1)] - d[sk(base + j - 1)];
            if (j < jmax) res[j] = s;
        }
    }
    __syncthreads();

    unsigned* hbuf = (unsigned*)d;
#pragma unroll
    for (int p = 0; p < 8; p++) {
        __half2 h = __floats2half2_rn(res[2 * p], res[2 * p + 1]);
        hbuf[hs((t << 3) + p)] = *(unsigned*)&h;
    }
    __syncthreads();

    unsigned* grow = g_tmp + (size_t)y * HP2;
#pragma unroll
    for (int k = 0; k < 8; k++) {
        int idx = t + (k << 8);
        if (idx < 2033) grow[idx] = hbuf[hs(idx)];
    }
}

// ---------------------------------------------------------------------------
// Pass 2: vertical 32-wide running box sum, batch-8 with front-issued loads.
// Smaller chunks (48 rows) -> 680 CTAs -> latency hidden by occupancy.
// Output stores are streaming (.cs) so the scratch stays in L2.
// ---------------------------------------------------------------------------
__global__ void __launch_bounds__(256)
col_pass(float* __restrict__ out)
{
    const int c2 = blockIdx.x * 256 + threadIdx.x;
    if (c2 >= 2033) return;
    const int x0 = c2 << 1;
    const bool x1ok = (x0 + 1) < WO;

    const int j0 = blockIdx.y * RCH2;
    const int n  = min(RCH2, WO - j0);
    const unsigned* col = g_tmp + c2;

    float s0 = 0.f, s1 = 0.f;
    {
        unsigned u[K];
#pragma unroll
        for (int r = 0; r < K; r++)
            u[r] = col[(size_t)(j0 + r) * HP2];
#pragma unroll
        for (int r = 0; r < K; r++) {
            float2 v = __half22float2(*(const __half2*)&u[r]);
            s0 += v.x; s1 += v.y;
        }
    }
    {
        float* o = out + (size_t)j0 * WO + x0;
        stcs(o, s0);
        if (x1ok) stcs(o + 1, s1);
    }

    for (int r = 1; r < n; r += 8) {
        const int m = min(8, n - r);
        unsigned ua[8], ub[8];
#pragma unroll
        for (int i = 0; i < 8; i++) {
            if (i < m) {
                ua[i] = col[(size_t)(j0 + r + i + K - 1) * HP2];
                ub[i] = col[(size_t)(j0 + r + i - 1) * HP2];
            }
        }
#pragma unroll
        for (int i = 0; i < 8; i++) {
            if (i < m) {
                float2 a = __half22float2(*(const __half2*)&ua[i]);
                float2 b = __half22float2(*(const __half2*)&ub[i]);
                s0 += a.x - b.x;
                s1 += a.y - b.y;
                float* o = out + (size_t)(j0 + r + i) * WO + x0;
                stcs(o, s0);
                if (x1ok) stcs(o + 1, s1);
            }
        }
    }
}

// ---------------------------------------------------------------------------
extern "C" void kernel_launch(void* const* d_in, const int* in_sizes, int n_in,
                              void* d_out, int out_size)
{
    const float* img = (const float*)d_in[0];   // [32,32]
    const float* som = (const float*)d_in[1];   // [4096,4096]
    const float* var = (const float*)d_in[2];   // [4096,4096]
    float*       out = (float*)d_out;           // [4065,4065]

    row_pass<<<H, 256>>>(img, som, var);

    dim3 grid2((2033 + 255) / 256,              // 8
               (WO + RCH2 - 1) / RCH2);         // 85 -> 680 CTAs
    col_pass<<<grid2, 256>>>(out);
}